// round 3
// baseline (speedup 1.0000x reference)
#include <cuda_runtime.h>
#include <cstdint>

// ----------------------------------------------------------------------------
// RBF kernel: K[i,j] = exp(-inv * (||x_i||^2 - 2 x_i.y_j + ||y_j||^2))
// N = M = 8192, D = 128, fp32.
// Strategy: legacy mma.sync TF32 (HMMA) with 3-pass Ootomo split.
// k-permuted fragment mapping -> fragments loaded directly from global with
// float2 LDGs (no smem, no ldmatrix, no __syncthreads in the mainloop).
// ----------------------------------------------------------------------------

#define NR 8192
#define DD 128

__device__ float g_x2[NR];
__device__ float g_y2[NR];
__device__ float g_Xhi[NR * DD];
__device__ float g_Xlo[NR * DD];
__device__ float g_Yhi[NR * DD];
__device__ float g_Ylo[NR * DD];

// split fp32 -> (hi, lo), both exactly tf32-representable
__device__ __forceinline__ void split1(float x, float& h, float& l) {
    uint32_t u;
    asm("cvt.rna.tf32.f32 %0, %1;" : "=r"(u) : "f"(x));
    h = __uint_as_float(u);
    float r = x - h;
    asm("cvt.rna.tf32.f32 %0, %1;" : "=r"(u) : "f"(r));
    l = __uint_as_float(u);
}

// m16n8k8 tf32 mma. A regs {a0,a1,a2,a3}: a0=(row g,   col q), a1=(row g+8, col q),
//                                         a2=(row g, col q+4), a3=(row g+8, col q+4)
// B regs {b0,b1}: b0=(k q, n g), b1=(k q+4, n g)   (g = lane/4, q = lane%4)
__device__ __forceinline__ void mma8(float* c, float2 a02, float2 a13, float2 b) {
    asm volatile(
        "mma.sync.aligned.m16n8k8.row.col.f32.tf32.tf32.f32 "
        "{%0,%1,%2,%3}, {%4,%5,%6,%7}, {%8,%9}, {%0,%1,%2,%3};"
        : "+f"(c[0]), "+f"(c[1]), "+f"(c[2]), "+f"(c[3])
        : "r"(__float_as_uint(a02.x)), "r"(__float_as_uint(a13.x)),
          "r"(__float_as_uint(a02.y)), "r"(__float_as_uint(a13.y)),
          "r"(__float_as_uint(b.x)),   "r"(__float_as_uint(b.y)));
}

// ---- prep: one warp per row: split into hi/lo + row norm -------------------
__global__ void prep_kernel(const float* __restrict__ X,
                            const float* __restrict__ Y,
                            int nX, int nY) {
    int warp = (blockIdx.x * blockDim.x + threadIdx.x) >> 5;
    int lane = threadIdx.x & 31;
    if (warp >= nX + nY) return;
    const float* src;
    float *dhi, *dlo, *dn;
    int row;
    if (warp < nX) { src = X; dhi = g_Xhi; dlo = g_Xlo; dn = g_x2; row = warp; }
    else           { src = Y; dhi = g_Yhi; dlo = g_Ylo; dn = g_y2; row = warp - nX; }

    float4 v = ((const float4*)(src + (size_t)row * DD))[lane];
    float4 h, l;
    split1(v.x, h.x, l.x);
    split1(v.y, h.y, l.y);
    split1(v.z, h.z, l.z);
    split1(v.w, h.w, l.w);
    ((float4*)(dhi + (size_t)row * DD))[lane] = h;
    ((float4*)(dlo + (size_t)row * DD))[lane] = l;

    float s = v.x * v.x + v.y * v.y + v.z * v.z + v.w * v.w;
    #pragma unroll
    for (int o = 16; o > 0; o >>= 1) s += __shfl_xor_sync(0xffffffffu, s, o);
    if (lane == 0) dn[row] = s;
}

// ---- main kernel: 128x128 CTA tile, 8 warps (4m x 2n), warp tile 32x64 -----
__global__ __launch_bounds__(256, 2)
void rbf_mma_kernel(const float* __restrict__ sigma,
                    float* __restrict__ out,
                    int Mtot) {
    const int tid = threadIdx.x;
    const int lane = tid & 31;
    const int wid = tid >> 5;
    const int q = lane & 3;        // lane % 4
    const int g = lane >> 2;       // lane / 4 (0..7)
    const int wm = wid & 3;        // 0..3
    const int wn = wid >> 2;       // 0..1

    const int rowW = blockIdx.y * 128 + wm * 32;   // warp's first M row
    const int colW = blockIdx.x * 128 + wn * 64;   // warp's first N col

    // per-thread fragment base pointers (k-permuted: thread owns span q*32..+31)
    const float* pAhi = g_Xhi + (size_t)(rowW + g) * DD + q * 32;
    const float* pAlo = g_Xlo + (size_t)(rowW + g) * DD + q * 32;
    const float* pBhi = g_Yhi + (size_t)(colW + g) * DD + q * 32;
    const float* pBlo = g_Ylo + (size_t)(colW + g) * DD + q * 32;

    float acc[2][8][4];
    #pragma unroll
    for (int mt = 0; mt < 2; mt++)
        #pragma unroll
        for (int j = 0; j < 8; j++)
            #pragma unroll
            for (int e = 0; e < 4; e++) acc[mt][j][e] = 0.0f;

    #pragma unroll 2
    for (int s = 0; s < 16; s++) {
        const int ko = 2 * s;

        // A fragments: rows g + {0,8,16,24}  (mt = r>>1, half = r&1)
        float2 ah[4], al[4];
        #pragma unroll
        for (int r = 0; r < 4; r++) {
            ah[r] = *(const float2*)(pAhi + (size_t)(r * 8) * DD + ko);
            al[r] = *(const float2*)(pAlo + (size_t)(r * 8) * DD + ko);
        }
        // B fragments: n-cols g + j*8
        float2 bh[8], bl[8];
        #pragma unroll
        for (int j = 0; j < 8; j++) {
            bh[j] = *(const float2*)(pBhi + (size_t)(j * 8) * DD + ko);
            bl[j] = *(const float2*)(pBlo + (size_t)(j * 8) * DD + ko);
        }

        #pragma unroll
        for (int mt = 0; mt < 2; mt++) {
            #pragma unroll
            for (int j = 0; j < 8; j++) {
                mma8(acc[mt][j], ah[mt * 2], ah[mt * 2 + 1], bh[j]);  // hi*hi
                mma8(acc[mt][j], ah[mt * 2], ah[mt * 2 + 1], bl[j]);  // hi*lo
                mma8(acc[mt][j], al[mt * 2], al[mt * 2 + 1], bh[j]);  // lo*hi
            }
        }
    }

    // ---- epilogue ----------------------------------------------------------
    float sv = sigma[0];
    float inv = 1.0f / (sv * sv + 1e-9f);

    #pragma unroll
    for (int mt = 0; mt < 2; mt++) {
        const int r0 = rowW + mt * 16 + g;
        const float x2a = g_x2[r0];
        const float x2b = g_x2[r0 + 8];
        #pragma unroll
        for (int j = 0; j < 8; j++) {
            const int cb = colW + j * 8 + 2 * q;
            const float y0 = g_y2[cb];
            const float y1 = g_y2[cb + 1];
            const float* c = acc[mt][j];
            float2 o0, o1;
            o0.x = __expf(inv * (2.0f * c[0] - x2a - y0));
            o0.y = __expf(inv * (2.0f * c[1] - x2a - y1));
            o1.x = __expf(inv * (2.0f * c[2] - x2b - y0));
            o1.y = __expf(inv * (2.0f * c[3] - x2b - y1));
            *(float2*)(out + (size_t)r0 * Mtot + cb)       = o0;
            *(float2*)(out + (size_t)(r0 + 8) * Mtot + cb) = o1;
        }
    }
}

// ----------------------------------------------------------------------------
extern "C" void kernel_launch(void* const* d_in, const int* in_sizes, int n_in,
                              void* d_out, int out_size) {
    const float* X = (const float*)d_in[0];
    const float* Y = (const float*)d_in[1];
    const float* sigma = (const float*)d_in[2];
    float* out = (float*)d_out;

    const int D = 128;
    const int n = in_sizes[0] / D;   // 8192
    const int m = in_sizes[1] / D;   // 8192

    {   // split + norms
        int warps = n + m;
        int threads = 256;
        int blocks = (warps * 32 + threads - 1) / threads;
        prep_kernel<<<blocks, threads>>>(X, Y, n, m);
    }

    {   // HMMA GEMM + exp
        dim3 grid(m / 128, n / 128);
        rbf_mma_kernel<<<grid, 256>>>(sigma, out, m);
    }
}

// round 6
// speedup vs baseline: 4.2188x; 4.2188x over previous
#include <cuda_runtime.h>
#include <cstdint>

// ----------------------------------------------------------------------------
// RBF: K[i,j] = exp(-inv * (||x_i||^2 - 2 x_i.y_j + ||y_j||^2)), 8192x8192x128.
// mma.sync m16n8k8 TF32, 3-pass Ootomo split (hi*hi + hi*lo + lo*hi).
// Smem double-buffer fed by plain LDG -> reg -> STS (deterministic, no cp.async).
// k-permuted smem layout: every fragment is one conflict-free LDS.128.
// ----------------------------------------------------------------------------

#define NR 8192
#define DD 128
#define NSTAGE 8              // 128 / 16
#define STAGE_BYTES 32768     // Ahi 8K | Alo 8K | Bhi 8K | Blo 8K

__device__ float g_x2[NR];
__device__ float g_y2[NR];
// stage-major permuted layout: idx = stage*(NR*16) + row*16 + off
__device__ float g_Xhi[NR * DD];
__device__ float g_Xlo[NR * DD];
__device__ float g_Yhi[NR * DD];
__device__ float g_Ylo[NR * DD];

__device__ __forceinline__ void split1(float x, float& h, float& l) {
    uint32_t u;
    asm("cvt.rna.tf32.f32 %0, %1;" : "=r"(u) : "f"(x));
    h = __uint_as_float(u);
    float r = x - h;
    asm("cvt.rna.tf32.f32 %0, %1;" : "=r"(u) : "f"(r));
    l = __uint_as_float(u);
}
__device__ __forceinline__ void mma8(float* c, float a0, float a1, float a2, float a3,
                                     float b0, float b1) {
    asm volatile(
        "mma.sync.aligned.m16n8k8.row.col.f32.tf32.tf32.f32 "
        "{%0,%1,%2,%3}, {%4,%5,%6,%7}, {%8,%9}, {%0,%1,%2,%3};"
        : "+f"(c[0]), "+f"(c[1]), "+f"(c[2]), "+f"(c[3])
        : "r"(__float_as_uint(a0)), "r"(__float_as_uint(a1)),
          "r"(__float_as_uint(a2)), "r"(__float_as_uint(a3)),
          "r"(__float_as_uint(b0)), "r"(__float_as_uint(b1)));
}

// ---- prep: one warp per row: permuted hi/lo split + row norm ---------------
// lane: stage = lane>>2, q' = lane&3; reads k = stage*16 + q' + {0,4,8,12};
// writes contiguous float4 at [stage][row][q'*4].
__global__ void prep_kernel(const float* __restrict__ X,
                            const float* __restrict__ Y,
                            int nX, int nY) {
    int warp = (blockIdx.x * blockDim.x + threadIdx.x) >> 5;
    int lane = threadIdx.x & 31;
    if (warp >= nX + nY) return;
    const float* src;
    float *dhi, *dlo, *dn;
    int row;
    if (warp < nX) { src = X; dhi = g_Xhi; dlo = g_Xlo; dn = g_x2; row = warp; }
    else           { src = Y; dhi = g_Yhi; dlo = g_Ylo; dn = g_y2; row = warp - nX; }

    const int stg = lane >> 2;
    const int qp = lane & 3;
    const float* r = src + (size_t)row * DD + stg * 16 + qp;
    float v0 = r[0], v1 = r[4], v2 = r[8], v3 = r[12];

    float4 h, l;
    split1(v0, h.x, l.x);
    split1(v1, h.y, l.y);
    split1(v2, h.z, l.z);
    split1(v3, h.w, l.w);
    size_t didx = (size_t)stg * (NR * 16) + (size_t)row * 16 + qp * 4;
    *(float4*)(dhi + didx) = h;
    *(float4*)(dlo + didx) = l;

    float s = v0 * v0 + v1 * v1 + v2 * v2 + v3 * v3;
    #pragma unroll
    for (int o = 16; o > 0; o >>= 1) s += __shfl_xor_sync(0xffffffffu, s, o);
    if (lane == 0) dn[row] = s;
}

// ---- main kernel: 128x128 CTA tile, 8 warps (4m x 2n), warp tile 32x64 -----
__global__ __launch_bounds__(256, 2)
void rbf_mma_kernel(const float* __restrict__ sigma,
                    float* __restrict__ out,
                    int Mtot) {
    extern __shared__ char smem[];
    const int tid = threadIdx.x;
    const int lane = tid & 31;
    const int wid = tid >> 5;
    const int q = lane & 3;
    const int g = lane >> 2;
    const int wm = wid & 3;        // 0..3
    const int wn = wid >> 2;       // 0..1

    const int row0 = blockIdx.y * 128;
    const int col0 = blockIdx.x * 128;
    const int rowW = row0 + wm * 32;
    const int colW = col0 + wn * 64;

    // fill mapping: region = tid>>6 (0:Ahi 1:Alo 2:Bhi 3:Blo), 8 x 16B chunks
    const int region = tid >> 6;
    const int t6 = tid & 63;
    const float* gsrc;
    int gr0;
    if      (region == 0) { gsrc = g_Xhi; gr0 = row0; }
    else if (region == 1) { gsrc = g_Xlo; gr0 = row0; }
    else if (region == 2) { gsrc = g_Yhi; gr0 = col0; }
    else                  { gsrc = g_Ylo; gr0 = col0; }
    // per-thread source base (chunk c at + (c*64)*4 floats)
    const float* gbase = gsrc + (size_t)gr0 * 16 + (size_t)t6 * 4;
    // per-thread dst offset WITHIN a stage buffer
    const int soff = region * 8192 + t6 * 16;

    float acc[2][8][4];
    #pragma unroll
    for (int mt = 0; mt < 2; mt++)
        #pragma unroll
        for (int j = 0; j < 8; j++)
            #pragma unroll
            for (int e = 0; e < 4; e++) acc[mt][j][e] = 0.0f;

    // ---- prologue: stage 0 -> buf 0 ----------------------------------------
    {
        float4 st[8];
        #pragma unroll
        for (int c = 0; c < 8; c++)
            st[c] = *(const float4*)(gbase + (size_t)c * 256);
        #pragma unroll
        for (int c = 0; c < 8; c++)
            *(float4*)(smem + soff + c * 1024) = st[c];
    }
    __syncthreads();

    // per-warp smem fragment offsets (within a buffer)
    const int aOff = (wm * 32 + g) * 64 + q * 16;
    const int bOff = 16384 + (wn * 64 + g) * 64 + q * 16;

    #pragma unroll 1
    for (int s = 0; s < NSTAGE; s++) {
        char* bs = smem + (s & 1) * STAGE_BYTES;
        char* bd = smem + ((s + 1) & 1) * STAGE_BYTES + soff;
        const float* gnext = gbase + (size_t)(s + 1) * (NR * 16);
        const bool pf = (s < NSTAGE - 1);

        float4 st[4];
        if (pf) {
            #pragma unroll
            for (int c = 0; c < 4; c++)
                st[c] = *(const float4*)(gnext + (size_t)c * 256);
        }

        // ---- mt = 0 (rows g, g+8) ----
        {
            float4 h0 = *(const float4*)(bs + aOff);
            float4 h1 = *(const float4*)(bs + aOff + 512);
            float4 l0 = *(const float4*)(bs + aOff + 8192);
            float4 l1 = *(const float4*)(bs + aOff + 8192 + 512);
            #pragma unroll
            for (int j = 0; j < 8; j++) {
                float4 bh = *(const float4*)(bs + bOff + j * 512);
                float4 bl = *(const float4*)(bs + bOff + 8192 + j * 512);
                float* c = acc[0][j];
                mma8(c, h0.x, h1.x, h0.y, h1.y, bh.x, bh.y);
                mma8(c, h0.x, h1.x, h0.y, h1.y, bl.x, bl.y);
                mma8(c, l0.x, l1.x, l0.y, l1.y, bh.x, bh.y);
                mma8(c, h0.z, h1.z, h0.w, h1.w, bh.z, bh.w);
                mma8(c, h0.z, h1.z, h0.w, h1.w, bl.z, bl.w);
                mma8(c, l0.z, l1.z, l0.w, l1.w, bh.z, bh.w);
            }
        }

        if (pf) {
            #pragma unroll
            for (int c = 0; c < 4; c++)
                *(float4*)(bd + c * 1024) = st[c];
            #pragma unroll
            for (int c = 0; c < 4; c++)
                st[c] = *(const float4*)(gnext + (size_t)(c + 4) * 256);
        }

        // ---- mt = 1 (rows g+16, g+24) ----
        {
            float4 h0 = *(const float4*)(bs + aOff + 1024);
            float4 h1 = *(const float4*)(bs + aOff + 1536);
            float4 l0 = *(const float4*)(bs + aOff + 8192 + 1024);
            float4 l1 = *(const float4*)(bs + aOff + 8192 + 1536);
            #pragma unroll
            for (int j = 0; j < 8; j++) {
                float4 bh = *(const float4*)(bs + bOff + j * 512);
                float4 bl = *(const float4*)(bs + bOff + 8192 + j * 512);
                float* c = acc[1][j];
                mma8(c, h0.x, h1.x, h0.y, h1.y, bh.x, bh.y);
                mma8(c, h0.x, h1.x, h0.y, h1.y, bl.x, bl.y);
                mma8(c, l0.x, l1.x, l0.y, l1.y, bh.x, bh.y);
                mma8(c, h0.z, h1.z, h0.w, h1.w, bh.z, bh.w);
                mma8(c, h0.z, h1.z, h0.w, h1.w, bl.z, bl.w);
                mma8(c, l0.z, l1.z, l0.w, l1.w, bh.z, bh.w);
            }
        }

        if (pf) {
            #pragma unroll
            for (int c = 0; c < 4; c++)
                *(float4*)(bd + (c + 4) * 1024) = st[c];
        }
        __syncthreads();
    }

    // ---- epilogue ----------------------------------------------------------
    float sv = sigma[0];
    float inv = 1.0f / (sv * sv + 1e-9f);

    #pragma unroll
    for (int mt = 0; mt < 2; mt++) {
        const int r0 = rowW + mt * 16 + g;
        const float x2a = g_x2[r0];
        const float x2b = g_x2[r0 + 8];
        #pragma unroll
        for (int j = 0; j < 8; j++) {
            const int cb = colW + j * 8 + 2 * q;
            const float y0 = g_y2[cb];
            const float y1 = g_y2[cb + 1];
            const float* c = acc[mt][j];
            float2 o0, o1;
            o0.x = __expf(inv * (2.0f * c[0] - x2a - y0));
            o0.y = __expf(inv * (2.0f * c[1] - x2a - y1));
            o1.x = __expf(inv * (2.0f * c[2] - x2b - y0));
            o1.y = __expf(inv * (2.0f * c[3] - x2b - y1));
            *(float2*)(out + (size_t)r0 * Mtot + cb)       = o0;
            *(float2*)(out + (size_t)(r0 + 8) * Mtot + cb) = o1;
        }
    }
}

// ----------------------------------------------------------------------------
extern "C" void kernel_launch(void* const* d_in, const int* in_sizes, int n_in,
                              void* d_out, int out_size) {
    const float* X = (const float*)d_in[0];
    const float* Y = (const float*)d_in[1];
    const float* sigma = (const float*)d_in[2];
    float* out = (float*)d_out;

    const int D = 128;
    const int n = in_sizes[0] / D;   // 8192
    const int m = in_sizes[1] / D;   // 8192

    // unconditional (no static guards); not a stream-ordered op -> capture-safe
    cudaFuncSetAttribute(rbf_mma_kernel,
                         cudaFuncAttributeMaxDynamicSharedMemorySize,
                         2 * STAGE_BYTES);

    {   // permuted hi/lo split + norms
        int warps = n + m;
        int threads = 256;
        int blocks = (warps * 32 + threads - 1) / threads;
        prep_kernel<<<blocks, threads>>>(X, Y, n, m);
    }

    {   // HMMA GEMM + exp
        dim3 grid(m / 128, n / 128);
        rbf_mma_kernel<<<grid, 256, 2 * STAGE_BYTES>>>(sigma, out, m);
    }
}

// round 7
// speedup vs baseline: 4.4873x; 1.0637x over previous
#include <cuda_runtime.h>
#include <cstdint>

// ----------------------------------------------------------------------------
// RBF: K[i,j] = exp(-inv * (||x_i||^2 - 2 x_i.y_j + ||y_j||^2)), 8192x8192x128.
// mma.sync m16n8k8 TF32, 3-pass Ootomo split (hi*hi + hi*lo + lo*hi).
// Smem double-buffer fed by plain LDG -> reg -> STS (deterministic).
// j-outer mainloop: A fragments live across stage, B loaded once per j.
// Stage loop unrolled x2 so smem addresses fold to immediates.
// Epilogue: warp-uniform underflow skip (exp(x)=0 exactly for x<-104).
// ----------------------------------------------------------------------------

#define NR 8192
#define DD 128
#define NSTAGE 8              // 128 / 16
#define STAGE_BYTES 32768     // Ahi 8K | Alo 8K | Bhi 8K | Blo 8K

__device__ float g_x2[NR];
__device__ float g_y2[NR];
// stage-major permuted layout: idx = stage*(NR*16) + row*16 + off
__device__ float g_Xhi[NR * DD];
__device__ float g_Xlo[NR * DD];
__device__ float g_Yhi[NR * DD];
__device__ float g_Ylo[NR * DD];

__device__ __forceinline__ void split1(float x, float& h, float& l) {
    uint32_t u;
    asm("cvt.rna.tf32.f32 %0, %1;" : "=r"(u) : "f"(x));
    h = __uint_as_float(u);
    float r = x - h;
    asm("cvt.rna.tf32.f32 %0, %1;" : "=r"(u) : "f"(r));
    l = __uint_as_float(u);
}
__device__ __forceinline__ void mma8(float* c, float a0, float a1, float a2, float a3,
                                     float b0, float b1) {
    asm volatile(
        "mma.sync.aligned.m16n8k8.row.col.f32.tf32.tf32.f32 "
        "{%0,%1,%2,%3}, {%4,%5,%6,%7}, {%8,%9}, {%0,%1,%2,%3};"
        : "+f"(c[0]), "+f"(c[1]), "+f"(c[2]), "+f"(c[3])
        : "r"(__float_as_uint(a0)), "r"(__float_as_uint(a1)),
          "r"(__float_as_uint(a2)), "r"(__float_as_uint(a3)),
          "r"(__float_as_uint(b0)), "r"(__float_as_uint(b1)));
}

// ---- prep: one warp per row: permuted hi/lo split + row norm ---------------
__global__ void prep_kernel(const float* __restrict__ X,
                            const float* __restrict__ Y,
                            int nX, int nY) {
    int warp = (blockIdx.x * blockDim.x + threadIdx.x) >> 5;
    int lane = threadIdx.x & 31;
    if (warp >= nX + nY) return;
    const float* src;
    float *dhi, *dlo, *dn;
    int row;
    if (warp < nX) { src = X; dhi = g_Xhi; dlo = g_Xlo; dn = g_x2; row = warp; }
    else           { src = Y; dhi = g_Yhi; dlo = g_Ylo; dn = g_y2; row = warp - nX; }

    const int stg = lane >> 2;
    const int qp = lane & 3;
    const float* r = src + (size_t)row * DD + stg * 16 + qp;
    float v0 = r[0], v1 = r[4], v2 = r[8], v3 = r[12];

    float4 h, l;
    split1(v0, h.x, l.x);
    split1(v1, h.y, l.y);
    split1(v2, h.z, l.z);
    split1(v3, h.w, l.w);
    size_t didx = (size_t)stg * (NR * 16) + (size_t)row * 16 + qp * 4;
    *(float4*)(dhi + didx) = h;
    *(float4*)(dlo + didx) = l;

    float s = v0 * v0 + v1 * v1 + v2 * v2 + v3 * v3;
    #pragma unroll
    for (int o = 16; o > 0; o >>= 1) s += __shfl_xor_sync(0xffffffffu, s, o);
    if (lane == 0) dn[row] = s;
}

// ---- main kernel: 128x128 CTA tile, 8 warps (4m x 2n), warp tile 32x64 -----
__global__ __launch_bounds__(256, 2)
void rbf_mma_kernel(const float* __restrict__ sigma,
                    float* __restrict__ out,
                    int Mtot) {
    extern __shared__ char smem[];
    const int tid = threadIdx.x;
    const int lane = tid & 31;
    const int wid = tid >> 5;
    const int q = lane & 3;
    const int g = lane >> 2;
    const int wm = wid & 3;        // 0..3
    const int wn = wid >> 2;       // 0..1

    const int row0 = blockIdx.y * 128;
    const int col0 = blockIdx.x * 128;
    const int rowW = row0 + wm * 32;
    const int colW = col0 + wn * 64;

    // fill mapping: region = tid>>6 (0:Ahi 1:Alo 2:Bhi 3:Blo), 8 x 16B chunks
    const int region = tid >> 6;
    const int t6 = tid & 63;
    const float* gsrc;
    int gr0;
    if      (region == 0) { gsrc = g_Xhi; gr0 = row0; }
    else if (region == 1) { gsrc = g_Xlo; gr0 = row0; }
    else if (region == 2) { gsrc = g_Yhi; gr0 = col0; }
    else                  { gsrc = g_Ylo; gr0 = col0; }
    const float* gbase = gsrc + (size_t)gr0 * 16 + (size_t)t6 * 4;
    const int soff = region * 8192 + t6 * 16;      // dst offset within a buffer

    float acc[2][8][4];
    #pragma unroll
    for (int mt = 0; mt < 2; mt++)
        #pragma unroll
        for (int j = 0; j < 8; j++)
            #pragma unroll
            for (int e = 0; e < 4; e++) acc[mt][j][e] = 0.0f;

    // ---- prologue: stage 0 -> buf 0 ----------------------------------------
    {
        float4 st[8];
        #pragma unroll
        for (int c = 0; c < 8; c++)
            st[c] = *(const float4*)(gbase + (size_t)c * 256);
        #pragma unroll
        for (int c = 0; c < 8; c++)
            *(float4*)(smem + soff + c * 1024) = st[c];
    }
    __syncthreads();

    // per-warp smem fragment offsets (within a buffer)
    const int aOff = (wm * 32 + g) * 64 + q * 16;
    const int bOff = 16384 + (wn * 64 + g) * 64 + q * 16;

    #pragma unroll 2
    for (int s = 0; s < NSTAGE; s++) {
        char* bs = smem + (s & 1) * STAGE_BYTES;          // const per unroll copy
        char* bd = smem + ((s + 1) & 1) * STAGE_BYTES + soff;
        const float* gnext = gbase + (size_t)(s + 1) * (NR * 16);
        const bool pf = (s < NSTAGE - 1);

        float4 st[4];
        if (pf) {
            #pragma unroll
            for (int c = 0; c < 4; c++)
                st[c] = *(const float4*)(gnext + (size_t)c * 256);
        }

        // A fragments for the whole stage (rows g+{0,8,16,24}, hi+lo)
        float4 ah[4], al[4];
        #pragma unroll
        for (int r = 0; r < 4; r++) {
            ah[r] = *(const float4*)(bs + aOff + r * 512);
            al[r] = *(const float4*)(bs + aOff + 8192 + r * 512);
        }

        #define JBODY(j_)                                                        \
        do {                                                                     \
            float4 bh = *(const float4*)(bs + bOff + (j_) * 512);                \
            float4 bl = *(const float4*)(bs + bOff + 8192 + (j_) * 512);         \
            float* c0 = acc[0][j_];                                              \
            mma8(c0, ah[0].x, ah[1].x, ah[0].y, ah[1].y, bh.x, bh.y);            \
            mma8(c0, ah[0].x, ah[1].x, ah[0].y, ah[1].y, bl.x, bl.y);            \
            mma8(c0, al[0].x, al[1].x, al[0].y, al[1].y, bh.x, bh.y);            \
            mma8(c0, ah[0].z, ah[1].z, ah[0].w, ah[1].w, bh.z, bh.w);            \
            mma8(c0, ah[0].z, ah[1].z, ah[0].w, ah[1].w, bl.z, bl.w);            \
            mma8(c0, al[0].z, al[1].z, al[0].w, al[1].w, bh.z, bh.w);            \
            float* c1 = acc[1][j_];                                              \
            mma8(c1, ah[2].x, ah[3].x, ah[2].y, ah[3].y, bh.x, bh.y);            \
            mma8(c1, ah[2].x, ah[3].x, ah[2].y, ah[3].y, bl.x, bl.y);            \
            mma8(c1, al[2].x, al[3].x, al[2].y, al[3].y, bh.x, bh.y);            \
            mma8(c1, ah[2].z, ah[3].z, ah[2].w, ah[3].w, bh.z, bh.w);            \
            mma8(c1, ah[2].z, ah[3].z, ah[2].w, ah[3].w, bl.z, bl.w);            \
            mma8(c1, al[2].z, al[3].z, al[2].w, al[3].w, bh.z, bh.w);            \
        } while (0)

        JBODY(0); JBODY(1); JBODY(2); JBODY(3);

        if (pf) {
            #pragma unroll
            for (int c = 0; c < 4; c++)
                *(float4*)(bd + c * 1024) = st[c];
            #pragma unroll
            for (int c = 0; c < 4; c++)
                st[c] = *(const float4*)(gnext + (size_t)(c + 4) * 256);
        }

        JBODY(4); JBODY(5); JBODY(6); JBODY(7);

        if (pf) {
            #pragma unroll
            for (int c = 0; c < 4; c++)
                *(float4*)(bd + (c + 4) * 1024) = st[c];
        }
        __syncthreads();
        #undef JBODY
    }

    // ---- epilogue ----------------------------------------------------------
    float sv = sigma[0];
    float inv = 1.0f / (sv * sv + 1e-9f);

    #pragma unroll
    for (int mt = 0; mt < 2; mt++) {
        const int r0 = rowW + mt * 16 + g;
        const float x2a = g_x2[r0];
        const float x2b = g_x2[r0 + 8];
        #pragma unroll
        for (int j = 0; j < 8; j++) {
            const int cb = colW + j * 8 + 2 * q;
            const float y0 = g_y2[cb];
            const float y1 = g_y2[cb + 1];
            const float* c = acc[mt][j];
            float a0 = inv * (2.0f * c[0] - x2a - y0);
            float a1 = inv * (2.0f * c[1] - x2a - y1);
            float a2 = inv * (2.0f * c[2] - x2b - y0);
            float a3 = inv * (2.0f * c[3] - x2b - y1);
            float mx = fmaxf(fmaxf(a0, a1), fmaxf(a2, a3));
            float2 o0, o1;
            // exp(x) == 0.0f exactly for x < -104 (below smallest subnormal);
            // warp-uniform skip avoids issuing MUFU for all-underflow groups.
            if (__any_sync(0xffffffffu, mx > -104.0f)) {
                o0.x = __expf(a0);
                o0.y = __expf(a1);
                o1.x = __expf(a2);
                o1.y = __expf(a3);
            } else {
                o0.x = 0.0f; o0.y = 0.0f; o1.x = 0.0f; o1.y = 0.0f;
            }
            *(float2*)(out + (size_t)r0 * Mtot + cb)       = o0;
            *(float2*)(out + (size_t)(r0 + 8) * Mtot + cb) = o1;
        }
    }
}

// ----------------------------------------------------------------------------
extern "C" void kernel_launch(void* const* d_in, const int* in_sizes, int n_in,
                              void* d_out, int out_size) {
    const float* X = (const float*)d_in[0];
    const float* Y = (const float*)d_in[1];
    const float* sigma = (const float*)d_in[2];
    float* out = (float*)d_out;

    const int D = 128;
    const int n = in_sizes[0] / D;   // 8192
    const int m = in_sizes[1] / D;   // 8192

    cudaFuncSetAttribute(rbf_mma_kernel,
                         cudaFuncAttributeMaxDynamicSharedMemorySize,
                         2 * STAGE_BYTES);

    {   // permuted hi/lo split + norms
        int warps = n + m;
        int threads = 256;
        int blocks = (warps * 32 + threads - 1) / threads;
        prep_kernel<<<blocks, threads>>>(X, Y, n, m);
    }

    {   // HMMA GEMM + exp
        dim3 grid(m / 128, n / 128);
        rbf_mma_kernel<<<grid, 256, 2 * STAGE_BYTES>>>(sigma, out, m);
    }
}

// round 8
// speedup vs baseline: 7.0210x; 1.5646x over previous
#include <cuda_runtime.h>
#include <cstdint>

// ----------------------------------------------------------------------------
// RBF: K[i,j] = exp(-inv * (||x_i||^2 - 2 x_i.y_j + ||y_j||^2)), 8192x8192x128.
// mma.sync m16n8k8 TF32, Ootomo split. Adaptive two-phase:
//   phase 1: hi*hi only. If the CTA's entire 128x128 tile provably underflows
//   fp32 exp (rigorous error bound on the missing cross terms), write zeros.
//   Otherwise phase 2 adds hi*lo + lo*hi (full 3-pass accuracy) + exp epilogue.
// ----------------------------------------------------------------------------

#define NR 8192
#define DD 128
#define NSTAGE 8
#define P1_STAGE 16384        // Ahi 8K | Bhi 8K
#define P2_STAGE 32768        // Ahi | Alo | Bhi | Blo
#define SMEM_TOTAL 65536

__device__ float g_x2[NR];
__device__ float g_y2[NR];
// stage-major permuted layout: idx = stage*(NR*16) + row*16 + off
__device__ float g_Xhi[NR * DD];
__device__ float g_Xlo[NR * DD];
__device__ float g_Yhi[NR * DD];
__device__ float g_Ylo[NR * DD];

__device__ __forceinline__ void split1(float x, float& h, float& l) {
    uint32_t u;
    asm("cvt.rna.tf32.f32 %0, %1;" : "=r"(u) : "f"(x));
    h = __uint_as_float(u);
    float r = x - h;
    asm("cvt.rna.tf32.f32 %0, %1;" : "=r"(u) : "f"(r));
    l = __uint_as_float(u);
}
__device__ __forceinline__ void mma8(float* c, float a0, float a1, float a2, float a3,
                                     float b0, float b1) {
    asm volatile(
        "mma.sync.aligned.m16n8k8.row.col.f32.tf32.tf32.f32 "
        "{%0,%1,%2,%3}, {%4,%5,%6,%7}, {%8,%9}, {%0,%1,%2,%3};"
        : "+f"(c[0]), "+f"(c[1]), "+f"(c[2]), "+f"(c[3])
        : "r"(__float_as_uint(a0)), "r"(__float_as_uint(a1)),
          "r"(__float_as_uint(a2)), "r"(__float_as_uint(a3)),
          "r"(__float_as_uint(b0)), "r"(__float_as_uint(b1)));
}

// ---- prep: one warp per row: permuted hi/lo split + row norm ---------------
__global__ void prep_kernel(const float* __restrict__ X,
                            const float* __restrict__ Y,
                            int nX, int nY) {
    int warp = (blockIdx.x * blockDim.x + threadIdx.x) >> 5;
    int lane = threadIdx.x & 31;
    if (warp >= nX + nY) return;
    const float* src;
    float *dhi, *dlo, *dn;
    int row;
    if (warp < nX) { src = X; dhi = g_Xhi; dlo = g_Xlo; dn = g_x2; row = warp; }
    else           { src = Y; dhi = g_Yhi; dlo = g_Ylo; dn = g_y2; row = warp - nX; }

    const int stg = lane >> 2;
    const int qp = lane & 3;
    const float* r = src + (size_t)row * DD + stg * 16 + qp;
    float v0 = r[0], v1 = r[4], v2 = r[8], v3 = r[12];

    float4 h, l;
    split1(v0, h.x, l.x);
    split1(v1, h.y, l.y);
    split1(v2, h.z, l.z);
    split1(v3, h.w, l.w);
    size_t didx = (size_t)stg * (NR * 16) + (size_t)row * 16 + qp * 4;
    *(float4*)(dhi + didx) = h;
    *(float4*)(dlo + didx) = l;

    float s = v0 * v0 + v1 * v1 + v2 * v2 + v3 * v3;
    #pragma unroll
    for (int o = 16; o > 0; o >>= 1) s += __shfl_xor_sync(0xffffffffu, s, o);
    if (lane == 0) dn[row] = s;
}

// ---- main kernel: 128x128 CTA tile, 8 warps (4m x 2n), warp tile 32x64 -----
__global__ __launch_bounds__(256, 2)
void rbf_mma_kernel(const float* __restrict__ sigma,
                    float* __restrict__ out,
                    int Mtot) {
    extern __shared__ char smem[];
    const int tid = threadIdx.x;
    const int lane = tid & 31;
    const int wid = tid >> 5;
    const int q = lane & 3;
    const int g = lane >> 2;
    const int wm = wid & 3;
    const int wn = wid >> 2;

    const int row0 = blockIdx.y * 128;
    const int col0 = blockIdx.x * 128;
    const int rowW = row0 + wm * 32;
    const int colW = col0 + wn * 64;

    float acc[2][8][4];
    #pragma unroll
    for (int mt = 0; mt < 2; mt++)
        #pragma unroll
        for (int j = 0; j < 8; j++)
            #pragma unroll
            for (int e = 0; e < 4; e++) acc[mt][j][e] = 0.0f;

    // ======================= PHASE 1: hi*hi ================================
    const int t7 = tid & 127;
    const bool isA = tid < 128;
    const float* g1 = (isA ? g_Xhi + (size_t)row0 * 16 : g_Yhi + (size_t)col0 * 16)
                      + (size_t)t7 * 4;
    const int soff1 = (isA ? 0 : 8192) + t7 * 16;

    {   // prologue: stage 0 -> buf 0
        float4 st[4];
        #pragma unroll
        for (int c = 0; c < 4; c++)
            st[c] = *(const float4*)(g1 + (size_t)c * 512);
        #pragma unroll
        for (int c = 0; c < 4; c++)
            *(float4*)(smem + soff1 + c * 2048) = st[c];
    }
    __syncthreads();

    const int aOff1 = (wm * 32 + g) * 64 + q * 16;
    const int bOff1 = 8192 + (wn * 64 + g) * 64 + q * 16;

    #pragma unroll 2
    for (int s = 0; s < NSTAGE; s++) {
        char* bs = smem + (s & 1) * P1_STAGE;
        char* bd = smem + ((s + 1) & 1) * P1_STAGE + soff1;
        const float* gn = g1 + (size_t)(s + 1) * (NR * 16);
        const bool pf = (s < NSTAGE - 1);

        float4 st[2];
        if (pf) { st[0] = *(const float4*)(gn); st[1] = *(const float4*)(gn + 512); }

        float4 ah[4];
        #pragma unroll
        for (int r = 0; r < 4; r++)
            ah[r] = *(const float4*)(bs + aOff1 + r * 512);

        #define J1(j_)                                                           \
        do {                                                                     \
            float4 bh = *(const float4*)(bs + bOff1 + (j_) * 512);               \
            float* c0 = acc[0][j_];                                              \
            mma8(c0, ah[0].x, ah[1].x, ah[0].y, ah[1].y, bh.x, bh.y);            \
            mma8(c0, ah[0].z, ah[1].z, ah[0].w, ah[1].w, bh.z, bh.w);            \
            float* c1 = acc[1][j_];                                              \
            mma8(c1, ah[2].x, ah[3].x, ah[2].y, ah[3].y, bh.x, bh.y);            \
            mma8(c1, ah[2].z, ah[3].z, ah[2].w, ah[3].w, bh.z, bh.w);            \
        } while (0)

        J1(0); J1(1); J1(2); J1(3);
        if (pf) {
            *(float4*)(bd) = st[0];
            *(float4*)(bd + 2048) = st[1];
            st[0] = *(const float4*)(gn + 1024);
            st[1] = *(const float4*)(gn + 1536);
        }
        J1(4); J1(5); J1(6); J1(7);
        if (pf) {
            *(float4*)(bd + 4096) = st[0];
            *(float4*)(bd + 6144) = st[1];
        }
        __syncthreads();
        #undef J1
    }

    // ======================= DECISION ======================================
    float sv = sigma[0];
    float inv = 1.0f / (sv * sv + 1e-9f);

    // Missing cross terms bounded: 2*|hi.lo+lo.hi| <= 2^-10*(x2+y2) < 0.002*(x2+y2).
    // If inv*(2*dot_hi - x2 - y2 + 0.002*(x2+y2)) < -105 for every element of
    // the tile, exp underflows to exactly 0.0f (fp32) for kernel AND reference.
    int need = 0;
    #pragma unroll
    for (int mt = 0; mt < 2; mt++) {
        const int r0 = rowW + mt * 16 + g;
        const float x2a = g_x2[r0];
        const float x2b = g_x2[r0 + 8];
        #pragma unroll
        for (int j = 0; j < 8; j++) {
            const int cb = colW + j * 8 + 2 * q;
            const float y0 = g_y2[cb];
            const float y1 = g_y2[cb + 1];
            const float* c = acc[mt][j];
            float u0 = inv * (2.0f * c[0] - x2a - y0 + 0.002f * (x2a + y0));
            float u1 = inv * (2.0f * c[1] - x2a - y1 + 0.002f * (x2a + y1));
            float u2 = inv * (2.0f * c[2] - x2b - y0 + 0.002f * (x2b + y0));
            float u3 = inv * (2.0f * c[3] - x2b - y1 + 0.002f * (x2b + y1));
            float mx = fmaxf(fmaxf(u0, u1), fmaxf(u2, u3));
            need |= (mx >= -105.0f);
        }
    }
    int doit = __syncthreads_or(need);

    if (!doit) {
        // whole tile underflows: coalesced zero write
        const int zr = tid >> 1;
        const int zc = (tid & 1) * 64;
        float4 z = make_float4(0.0f, 0.0f, 0.0f, 0.0f);
        float* dst = out + (size_t)(row0 + zr) * Mtot + col0 + zc;
        #pragma unroll
        for (int c = 0; c < 16; c++)
            *(float4*)(dst + c * 4) = z;
        return;
    }

    // ======================= PHASE 2: hi*lo + lo*hi ========================
    const int region = tid >> 6;
    const int t6 = tid & 63;
    const float* gsrc2;
    int gr2;
    if      (region == 0) { gsrc2 = g_Xhi; gr2 = row0; }
    else if (region == 1) { gsrc2 = g_Xlo; gr2 = row0; }
    else if (region == 2) { gsrc2 = g_Yhi; gr2 = col0; }
    else                  { gsrc2 = g_Ylo; gr2 = col0; }
    const float* g2 = gsrc2 + (size_t)gr2 * 16 + (size_t)t6 * 4;
    const int soff2 = region * 8192 + t6 * 16;

    {   // prologue: stage 0 -> buf 0
        float4 st[8];
        #pragma unroll
        for (int c = 0; c < 8; c++)
            st[c] = *(const float4*)(g2 + (size_t)c * 256);
        #pragma unroll
        for (int c = 0; c < 8; c++)
            *(float4*)(smem + soff2 + c * 1024) = st[c];
    }
    __syncthreads();

    const int aOff2 = (wm * 32 + g) * 64 + q * 16;
    const int bOff2 = 16384 + (wn * 64 + g) * 64 + q * 16;

    #pragma unroll 2
    for (int s = 0; s < NSTAGE; s++) {
        char* bs = smem + (s & 1) * P2_STAGE;
        char* bd = smem + ((s + 1) & 1) * P2_STAGE + soff2;
        const float* gn = g2 + (size_t)(s + 1) * (NR * 16);
        const bool pf = (s < NSTAGE - 1);

        float4 st[4];
        if (pf) {
            #pragma unroll
            for (int c = 0; c < 4; c++)
                st[c] = *(const float4*)(gn + (size_t)c * 256);
        }

        float4 ah[4], al[4];
        #pragma unroll
        for (int r = 0; r < 4; r++) {
            ah[r] = *(const float4*)(bs + aOff2 + r * 512);
            al[r] = *(const float4*)(bs + aOff2 + 8192 + r * 512);
        }

        #define J2(j_)                                                           \
        do {                                                                     \
            float4 bh = *(const float4*)(bs + bOff2 + (j_) * 512);               \
            float4 bl = *(const float4*)(bs + bOff2 + 8192 + (j_) * 512);        \
            float* c0 = acc[0][j_];                                              \
            mma8(c0, ah[0].x, ah[1].x, ah[0].y, ah[1].y, bl.x, bl.y);            \
            mma8(c0, al[0].x, al[1].x, al[0].y, al[1].y, bh.x, bh.y);            \
            mma8(c0, ah[0].z, ah[1].z, ah[0].w, ah[1].w, bl.z, bl.w);            \
            mma8(c0, al[0].z, al[1].z, al[0].w, al[1].w, bh.z, bh.w);            \
            float* c1 = acc[1][j_];                                              \
            mma8(c1, ah[2].x, ah[3].x, ah[2].y, ah[3].y, bl.x, bl.y);            \
            mma8(c1, al[2].x, al[3].x, al[2].y, al[3].y, bh.x, bh.y);            \
            mma8(c1, ah[2].z, ah[3].z, ah[2].w, ah[3].w, bl.z, bl.w);            \
            mma8(c1, al[2].z, al[3].z, al[2].w, al[3].w, bh.z, bh.w);            \
        } while (0)

        J2(0); J2(1); J2(2); J2(3);
        if (pf) {
            #pragma unroll
            for (int c = 0; c < 4; c++)
                *(float4*)(bd + c * 1024) = st[c];
            #pragma unroll
            for (int c = 0; c < 4; c++)
                st[c] = *(const float4*)(gn + (size_t)(c + 4) * 256);
        }
        J2(4); J2(5); J2(6); J2(7);
        if (pf) {
            #pragma unroll
            for (int c = 0; c < 4; c++)
                *(float4*)(bd + (c + 4) * 1024) = st[c];
        }
        __syncthreads();
        #undef J2
    }

    // ======================= EPILOGUE ======================================
    #pragma unroll
    for (int mt = 0; mt < 2; mt++) {
        const int r0 = rowW + mt * 16 + g;
        const float x2a = g_x2[r0];
        const float x2b = g_x2[r0 + 8];
        #pragma unroll
        for (int j = 0; j < 8; j++) {
            const int cb = colW + j * 8 + 2 * q;
            const float y0 = g_y2[cb];
            const float y1 = g_y2[cb + 1];
            const float* c = acc[mt][j];
            float a0 = inv * (2.0f * c[0] - x2a - y0);
            float a1 = inv * (2.0f * c[1] - x2a - y1);
            float a2 = inv * (2.0f * c[2] - x2b - y0);
            float a3 = inv * (2.0f * c[3] - x2b - y1);
            float mx = fmaxf(fmaxf(a0, a1), fmaxf(a2, a3));
            float2 o0, o1;
            if (__any_sync(0xffffffffu, mx > -104.0f)) {
                o0.x = __expf(a0);
                o0.y = __expf(a1);
                o1.x = __expf(a2);
                o1.y = __expf(a3);
            } else {
                o0.x = 0.0f; o0.y = 0.0f; o1.x = 0.0f; o1.y = 0.0f;
            }
            *(float2*)(out + (size_t)r0 * Mtot + cb)       = o0;
            *(float2*)(out + (size_t)(r0 + 8) * Mtot + cb) = o1;
        }
    }
}

// ----------------------------------------------------------------------------
extern "C" void kernel_launch(void* const* d_in, const int* in_sizes, int n_in,
                              void* d_out, int out_size) {
    const float* X = (const float*)d_in[0];
    const float* Y = (const float*)d_in[1];
    const float* sigma = (const float*)d_in[2];
    float* out = (float*)d_out;

    const int D = 128;
    const int n = in_sizes[0] / D;   // 8192
    const int m = in_sizes[1] / D;   // 8192

    cudaFuncSetAttribute(rbf_mma_kernel,
                         cudaFuncAttributeMaxDynamicSharedMemorySize, SMEM_TOTAL);

    {   // permuted hi/lo split + norms
        int warps = n + m;
        int threads = 256;
        int blocks = (warps * 32 + threads - 1) / threads;
        prep_kernel<<<blocks, threads>>>(X, Y, n, m);
    }

    {   // adaptive HMMA GEMM + exp
        dim3 grid(m / 128, n / 128);
        rbf_mma_kernel<<<grid, 256, SMEM_TOTAL>>>(sigma, out, m);
    }
}

// round 9
// speedup vs baseline: 8.6439x; 1.2312x over previous
#include <cuda_runtime.h>
#include <cstdint>

// ----------------------------------------------------------------------------
// RBF: K[i,j] = exp(-inv * (||x_i||^2 - 2 x_i.y_j + ||y_j||^2)), 8192x8192x128.
// mma.sync m16n8k8 TF32, Ootomo split. Adaptive two-phase:
//   phase 1: hi*hi only. If the CTA's entire 128x128 tile provably underflows
//   fp32 exp (rigorous error bound on the missing cross terms), write zeros
//   (fully coalesced). Otherwise phase 2 adds hi*lo + lo*hi (full 3-pass
//   accuracy) + exp epilogue.
// ----------------------------------------------------------------------------

#define NR 8192
#define DD 128
#define NSTAGE 8
#define P1_STAGE 16384        // Ahi 8K | Bhi 8K
#define P2_STAGE 32768        // Ahi | Alo | Bhi | Blo
#define SMEM_TOTAL 65536

__device__ float g_x2[NR];
__device__ float g_y2[NR];
// stage-major permuted layout: idx = stage*(NR*16) + row*16 + off
__device__ float g_Xhi[NR * DD];
__device__ float g_Xlo[NR * DD];
__device__ float g_Yhi[NR * DD];
__device__ float g_Ylo[NR * DD];

__device__ __forceinline__ void split1(float x, float& h, float& l) {
    uint32_t u;
    asm("cvt.rna.tf32.f32 %0, %1;" : "=r"(u) : "f"(x));
    h = __uint_as_float(u);
    float r = x - h;
    asm("cvt.rna.tf32.f32 %0, %1;" : "=r"(u) : "f"(r));
    l = __uint_as_float(u);
}
__device__ __forceinline__ void mma8(float* c, float a0, float a1, float a2, float a3,
                                     float b0, float b1) {
    asm volatile(
        "mma.sync.aligned.m16n8k8.row.col.f32.tf32.tf32.f32 "
        "{%0,%1,%2,%3}, {%4,%5,%6,%7}, {%8,%9}, {%0,%1,%2,%3};"
        : "+f"(c[0]), "+f"(c[1]), "+f"(c[2]), "+f"(c[3])
        : "r"(__float_as_uint(a0)), "r"(__float_as_uint(a1)),
          "r"(__float_as_uint(a2)), "r"(__float_as_uint(a3)),
          "r"(__float_as_uint(b0)), "r"(__float_as_uint(b1)));
}

// ---- prep: one warp per row: permuted hi/lo split + row norm ---------------
__global__ void prep_kernel(const float* __restrict__ X,
                            const float* __restrict__ Y,
                            int nX, int nY) {
    int warp = (blockIdx.x * blockDim.x + threadIdx.x) >> 5;
    int lane = threadIdx.x & 31;
    if (warp >= nX + nY) return;
    const float* src;
    float *dhi, *dlo, *dn;
    int row;
    if (warp < nX) { src = X; dhi = g_Xhi; dlo = g_Xlo; dn = g_x2; row = warp; }
    else           { src = Y; dhi = g_Yhi; dlo = g_Ylo; dn = g_y2; row = warp - nX; }

    const int stg = lane >> 2;
    const int qp = lane & 3;
    const float* r = src + (size_t)row * DD + stg * 16 + qp;
    float v0 = r[0], v1 = r[4], v2 = r[8], v3 = r[12];

    float4 h, l;
    split1(v0, h.x, l.x);
    split1(v1, h.y, l.y);
    split1(v2, h.z, l.z);
    split1(v3, h.w, l.w);
    size_t didx = (size_t)stg * (NR * 16) + (size_t)row * 16 + qp * 4;
    *(float4*)(dhi + didx) = h;
    *(float4*)(dlo + didx) = l;

    float s = v0 * v0 + v1 * v1 + v2 * v2 + v3 * v3;
    #pragma unroll
    for (int o = 16; o > 0; o >>= 1) s += __shfl_xor_sync(0xffffffffu, s, o);
    if (lane == 0) dn[row] = s;
}

// ---- main kernel: 128x128 CTA tile, 8 warps (4m x 2n), warp tile 32x64 -----
__global__ __launch_bounds__(256, 2)
void rbf_mma_kernel(const float* __restrict__ sigma,
                    float* __restrict__ out,
                    int Mtot) {
    extern __shared__ char smem[];
    const int tid = threadIdx.x;
    const int lane = tid & 31;
    const int wid = tid >> 5;
    const int q = lane & 3;
    const int g = lane >> 2;
    const int wm = wid & 3;
    const int wn = wid >> 2;

    const int row0 = blockIdx.y * 128;
    const int col0 = blockIdx.x * 128;
    const int rowW = row0 + wm * 32;
    const int colW = col0 + wn * 64;

    float acc[2][8][4];
    #pragma unroll
    for (int mt = 0; mt < 2; mt++)
        #pragma unroll
        for (int j = 0; j < 8; j++)
            #pragma unroll
            for (int e = 0; e < 4; e++) acc[mt][j][e] = 0.0f;

    // ======================= PHASE 1: hi*hi ================================
    const int t7 = tid & 127;
    const bool isA = tid < 128;
    const float* g1 = (isA ? g_Xhi + (size_t)row0 * 16 : g_Yhi + (size_t)col0 * 16)
                      + (size_t)t7 * 4;
    const int soff1 = (isA ? 0 : 8192) + t7 * 16;

    {   // prologue: stage 0 -> buf 0
        float4 st[4];
        #pragma unroll
        for (int c = 0; c < 4; c++)
            st[c] = *(const float4*)(g1 + (size_t)c * 512);
        #pragma unroll
        for (int c = 0; c < 4; c++)
            *(float4*)(smem + soff1 + c * 2048) = st[c];
    }
    __syncthreads();

    const int aOff1 = (wm * 32 + g) * 64 + q * 16;
    const int bOff1 = 8192 + (wn * 64 + g) * 64 + q * 16;

    #pragma unroll 2
    for (int s = 0; s < NSTAGE; s++) {
        char* bs = smem + (s & 1) * P1_STAGE;
        char* bd = smem + ((s + 1) & 1) * P1_STAGE + soff1;
        const float* gn = g1 + (size_t)(s + 1) * (NR * 16);
        const bool pf = (s < NSTAGE - 1);

        float4 st[2];
        if (pf) { st[0] = *(const float4*)(gn); st[1] = *(const float4*)(gn + 512); }

        float4 ah[4];
        #pragma unroll
        for (int r = 0; r < 4; r++)
            ah[r] = *(const float4*)(bs + aOff1 + r * 512);

        #define J1(j_)                                                           \
        do {                                                                     \
            float4 bh = *(const float4*)(bs + bOff1 + (j_) * 512);               \
            float* c0 = acc[0][j_];                                              \
            mma8(c0, ah[0].x, ah[1].x, ah[0].y, ah[1].y, bh.x, bh.y);            \
            mma8(c0, ah[0].z, ah[1].z, ah[0].w, ah[1].w, bh.z, bh.w);            \
            float* c1 = acc[1][j_];                                              \
            mma8(c1, ah[2].x, ah[3].x, ah[2].y, ah[3].y, bh.x, bh.y);            \
            mma8(c1, ah[2].z, ah[3].z, ah[2].w, ah[3].w, bh.z, bh.w);            \
        } while (0)

        J1(0); J1(1); J1(2); J1(3);
        if (pf) {
            *(float4*)(bd) = st[0];
            *(float4*)(bd + 2048) = st[1];
            st[0] = *(const float4*)(gn + 1024);
            st[1] = *(const float4*)(gn + 1536);
        }
        J1(4); J1(5); J1(6); J1(7);
        if (pf) {
            *(float4*)(bd + 4096) = st[0];
            *(float4*)(bd + 6144) = st[1];
        }
        __syncthreads();
        #undef J1
    }

    // ======================= DECISION ======================================
    float sv = sigma[0];
    float inv = 1.0f / (sv * sv + 1e-9f);

    // Missing cross terms bounded: 2*|hi.lo+lo.hi| <= 2^-10*(x2+y2) < 0.002*(x2+y2).
    // If inv*(2*dot_hi - x2 - y2 + 0.002*(x2+y2)) < -105 for every element of
    // the tile, exp underflows to exactly 0.0f (fp32) for kernel AND reference.
    int need = 0;
    #pragma unroll
    for (int mt = 0; mt < 2; mt++) {
        const int r0 = rowW + mt * 16 + g;
        const float x2a = g_x2[r0];
        const float x2b = g_x2[r0 + 8];
        #pragma unroll
        for (int j = 0; j < 8; j++) {
            const int cb = colW + j * 8 + 2 * q;
            const float y0 = g_y2[cb];
            const float y1 = g_y2[cb + 1];
            const float* c = acc[mt][j];
            float u0 = inv * (2.0f * c[0] - x2a - y0 + 0.002f * (x2a + y0));
            float u1 = inv * (2.0f * c[1] - x2a - y1 + 0.002f * (x2a + y1));
            float u2 = inv * (2.0f * c[2] - x2b - y0 + 0.002f * (x2b + y0));
            float u3 = inv * (2.0f * c[3] - x2b - y1 + 0.002f * (x2b + y1));
            float mx = fmaxf(fmaxf(u0, u1), fmaxf(u2, u3));
            need |= (mx >= -105.0f);
        }
    }
    int doit = __syncthreads_or(need);

    if (!doit) {
        // whole tile underflows: fully coalesced zero write.
        // warp w owns rows wid*16 .. wid*16+15; per row, lanes cover 128 floats
        // contiguously (one 512B wavefront per STG.128).
        float4 z = make_float4(0.0f, 0.0f, 0.0f, 0.0f);
        float* dst = out + (size_t)(row0 + wid * 16) * Mtot + col0 + lane * 4;
        #pragma unroll
        for (int r = 0; r < 16; r++)
            *(float4*)(dst + (size_t)r * Mtot) = z;
        return;
    }

    // ======================= PHASE 2: hi*lo + lo*hi ========================
    const int region = tid >> 6;
    const int t6 = tid & 63;
    const float* gsrc2;
    int gr2;
    if      (region == 0) { gsrc2 = g_Xhi; gr2 = row0; }
    else if (region == 1) { gsrc2 = g_Xlo; gr2 = row0; }
    else if (region == 2) { gsrc2 = g_Yhi; gr2 = col0; }
    else                  { gsrc2 = g_Ylo; gr2 = col0; }
    const float* g2 = gsrc2 + (size_t)gr2 * 16 + (size_t)t6 * 4;
    const int soff2 = region * 8192 + t6 * 16;

    {   // prologue: stage 0 -> buf 0
        float4 st[8];
        #pragma unroll
        for (int c = 0; c < 8; c++)
            st[c] = *(const float4*)(g2 + (size_t)c * 256);
        #pragma unroll
        for (int c = 0; c < 8; c++)
            *(float4*)(smem + soff2 + c * 1024) = st[c];
    }
    __syncthreads();

    const int aOff2 = (wm * 32 + g) * 64 + q * 16;
    const int bOff2 = 16384 + (wn * 64 + g) * 64 + q * 16;

    #pragma unroll 2
    for (int s = 0; s < NSTAGE; s++) {
        char* bs = smem + (s & 1) * P2_STAGE;
        char* bd = smem + ((s + 1) & 1) * P2_STAGE + soff2;
        const float* gn = g2 + (size_t)(s + 1) * (NR * 16);
        const bool pf = (s < NSTAGE - 1);

        float4 st[4];
        if (pf) {
            #pragma unroll
            for (int c = 0; c < 4; c++)
                st[c] = *(const float4*)(gn + (size_t)c * 256);
        }

        float4 ah[4], al[4];
        #pragma unroll
        for (int r = 0; r < 4; r++) {
            ah[r] = *(const float4*)(bs + aOff2 + r * 512);
            al[r] = *(const float4*)(bs + aOff2 + 8192 + r * 512);
        }

        #define J2(j_)                                                           \
        do {                                                                     \
            float4 bh = *(const float4*)(bs + bOff2 + (j_) * 512);               \
            float4 bl = *(const float4*)(bs + bOff2 + 8192 + (j_) * 512);        \
            float* c0 = acc[0][j_];                                              \
            mma8(c0, ah[0].x, ah[1].x, ah[0].y, ah[1].y, bl.x, bl.y);            \
            mma8(c0, al[0].x, al[1].x, al[0].y, al[1].y, bh.x, bh.y);            \
            mma8(c0, ah[0].z, ah[1].z, ah[0].w, ah[1].w, bl.z, bl.w);            \
            mma8(c0, al[0].z, al[1].z, al[0].w, al[1].w, bh.z, bh.w);            \
            float* c1 = acc[1][j_];                                              \
            mma8(c1, ah[2].x, ah[3].x, ah[2].y, ah[3].y, bl.x, bl.y);            \
            mma8(c1, al[2].x, al[3].x, al[2].y, al[3].y, bh.x, bh.y);            \
            mma8(c1, ah[2].z, ah[3].z, ah[2].w, ah[3].w, bl.z, bl.w);            \
            mma8(c1, al[2].z, al[3].z, al[2].w, al[3].w, bh.z, bh.w);            \
        } while (0)

        J2(0); J2(1); J2(2); J2(3);
        if (pf) {
            #pragma unroll
            for (int c = 0; c < 4; c++)
                *(float4*)(bd + c * 1024) = st[c];
            #pragma unroll
            for (int c = 0; c < 4; c++)
                st[c] = *(const float4*)(gn + (size_t)(c + 4) * 256);
        }
        J2(4); J2(5); J2(6); J2(7);
        if (pf) {
            #pragma unroll
            for (int c = 0; c < 4; c++)
                *(float4*)(bd + (c + 4) * 1024) = st[c];
        }
        __syncthreads();
        #undef J2
    }

    // ======================= EPILOGUE ======================================
    #pragma unroll
    for (int mt = 0; mt < 2; mt++) {
        const int r0 = rowW + mt * 16 + g;
        const float x2a = g_x2[r0];
        const float x2b = g_x2[r0 + 8];
        #pragma unroll
        for (int j = 0; j < 8; j++) {
            const int cb = colW + j * 8 + 2 * q;
            const float y0 = g_y2[cb];
            const float y1 = g_y2[cb + 1];
            const float* c = acc[mt][j];
            float a0 = inv * (2.0f * c[0] - x2a - y0);
            float a1 = inv * (2.0f * c[1] - x2a - y1);
            float a2 = inv * (2.0f * c[2] - x2b - y0);
            float a3 = inv * (2.0f * c[3] - x2b - y1);
            float mx = fmaxf(fmaxf(a0, a1), fmaxf(a2, a3));
            float2 o0, o1;
            if (__any_sync(0xffffffffu, mx > -104.0f)) {
                o0.x = __expf(a0);
                o0.y = __expf(a1);
                o1.x = __expf(a2);
                o1.y = __expf(a3);
            } else {
                o0.x = 0.0f; o0.y = 0.0f; o1.x = 0.0f; o1.y = 0.0f;
            }
            *(float2*)(out + (size_t)r0 * Mtot + cb)       = o0;
            *(float2*)(out + (size_t)(r0 + 8) * Mtot + cb) = o1;
        }
    }
}

// ----------------------------------------------------------------------------
extern "C" void kernel_launch(void* const* d_in, const int* in_sizes, int n_in,
                              void* d_out, int out_size) {
    const float* X = (const float*)d_in[0];
    const float* Y = (const float*)d_in[1];
    const float* sigma = (const float*)d_in[2];
    float* out = (float*)d_out;

    const int D = 128;
    const int n = in_sizes[0] / D;   // 8192
    const int m = in_sizes[1] / D;   // 8192

    cudaFuncSetAttribute(rbf_mma_kernel,
                         cudaFuncAttributeMaxDynamicSharedMemorySize, SMEM_TOTAL);

    {   // permuted hi/lo split + norms
        int warps = n + m;
        int threads = 256;
        int blocks = (warps * 32 + threads - 1) / threads;
        prep_kernel<<<blocks, threads>>>(X, Y, n, m);
    }

    {   // adaptive HMMA GEMM + exp
        dim3 grid(m / 128, n / 128);
        rbf_mma_kernel<<<grid, 256, SMEM_TOTAL>>>(sigma, out, m);
    }
}

// round 10
// speedup vs baseline: 13.1588x; 1.5223x over previous
#include <cuda_runtime.h>
#include <cstdint>

// ----------------------------------------------------------------------------
// RBF: K[i,j] = exp(-inv * (||x_i||^2 - 2 x_i.y_j + ||y_j||^2)), 8192x8192x128.
// Adaptive two-phase:
//   phase 1: bf16 m16n8k16 HMMA dot estimate. If the CTA's whole 128x128 tile
//   provably underflows fp32 exp (rigorous bf16 error bound 2^-9*(x2+y2) on
//   the dot, margin 0.008), stream zeros and exit.
//   phase 2 (rare): zero acc, full 3-pass tf32 Ootomo GEMM + exp epilogue.
// ----------------------------------------------------------------------------

#define NR 8192
#define DD 128
#define NCHUNK 4              // phase-1 k chunks of 32
#define P1_STAGE 16384        // A(bf16) 8K | B(bf16) 8K
#define NSTAGE2 8             // phase-2 k stages of 16
#define P2_STAGE 32768        // Ahi | Alo | Bhi | Blo
#define SMEM_TOTAL 65536

__device__ float g_x2[NR];
__device__ float g_y2[NR];
// bf16 permuted, chunk-major: uint4 idx = chunk*(NR*4) + row*4 + q
__device__ uint4 g_Xb[NR * 16];
__device__ uint4 g_Yb[NR * 16];
// tf32 hi/lo, stage-major permuted (phase 2): idx = stage*(NR*16) + row*16 + off
__device__ float g_Xhi[NR * DD];
__device__ float g_Xlo[NR * DD];
__device__ float g_Yhi[NR * DD];
__device__ float g_Ylo[NR * DD];

__device__ __forceinline__ void split1(float x, float& h, float& l) {
    uint32_t u;
    asm("cvt.rna.tf32.f32 %0, %1;" : "=r"(u) : "f"(x));
    h = __uint_as_float(u);
    float r = x - h;
    asm("cvt.rna.tf32.f32 %0, %1;" : "=r"(u) : "f"(r));
    l = __uint_as_float(u);
}
__device__ __forceinline__ uint32_t pack_bf16(float lo, float hi) {
    uint32_t r;
    asm("cvt.rn.bf16x2.f32 %0, %1, %2;" : "=r"(r) : "f"(hi), "f"(lo));
    return r;
}
__device__ __forceinline__ void mma16(float* c, uint32_t a0, uint32_t a1,
                                      uint32_t a2, uint32_t a3,
                                      uint32_t b0, uint32_t b1) {
    asm volatile(
        "mma.sync.aligned.m16n8k16.row.col.f32.bf16.bf16.f32 "
        "{%0,%1,%2,%3}, {%4,%5,%6,%7}, {%8,%9}, {%0,%1,%2,%3};"
        : "+f"(c[0]), "+f"(c[1]), "+f"(c[2]), "+f"(c[3])
        : "r"(a0), "r"(a1), "r"(a2), "r"(a3), "r"(b0), "r"(b1));
}
__device__ __forceinline__ void mma8(float* c, float a0, float a1, float a2, float a3,
                                     float b0, float b1) {
    asm volatile(
        "mma.sync.aligned.m16n8k8.row.col.f32.tf32.tf32.f32 "
        "{%0,%1,%2,%3}, {%4,%5,%6,%7}, {%8,%9}, {%0,%1,%2,%3};"
        : "+f"(c[0]), "+f"(c[1]), "+f"(c[2]), "+f"(c[3])
        : "r"(__float_as_uint(a0)), "r"(__float_as_uint(a1)),
          "r"(__float_as_uint(a2)), "r"(__float_as_uint(a3)),
          "r"(__float_as_uint(b0)), "r"(__float_as_uint(b1)));
}

// ---- prep: one warp per row -------------------------------------------------
// tf32 part: lane stg=lane>>2, qp=lane&3; k = stg*16 + qp + {0,4,8,12}.
// bf16 part: lanes 0..15: chunk c=lane>>2, q=lane&3; packs k-sets
//   {2q,2q+1,2q+8,2q+9} for both k16-halves of the 32-chunk into one uint4.
__global__ void prep_kernel(const float* __restrict__ X,
                            const float* __restrict__ Y,
                            int nX, int nY) {
    int warp = (blockIdx.x * blockDim.x + threadIdx.x) >> 5;
    int lane = threadIdx.x & 31;
    if (warp >= nX + nY) return;
    const float* src;
    float *dhi, *dlo, *dn;
    uint4* db;
    int row;
    if (warp < nX) { src = X; dhi = g_Xhi; dlo = g_Xlo; dn = g_x2; db = g_Xb; row = warp; }
    else           { src = Y; dhi = g_Yhi; dlo = g_Ylo; dn = g_y2; db = g_Yb; row = warp - nX; }

    // tf32 permuted hi/lo
    const int stg = lane >> 2;
    const int qp = lane & 3;
    const float* r = src + (size_t)row * DD + stg * 16 + qp;
    float v0 = r[0], v1 = r[4], v2 = r[8], v3 = r[12];
    float4 h, l;
    split1(v0, h.x, l.x);
    split1(v1, h.y, l.y);
    split1(v2, h.z, l.z);
    split1(v3, h.w, l.w);
    size_t didx = (size_t)stg * (NR * 16) + (size_t)row * 16 + qp * 4;
    *(float4*)(dhi + didx) = h;
    *(float4*)(dlo + didx) = l;

    // row norm
    float s = v0 * v0 + v1 * v1 + v2 * v2 + v3 * v3;
    #pragma unroll
    for (int o = 16; o > 0; o >>= 1) s += __shfl_xor_sync(0xffffffffu, s, o);
    if (lane == 0) dn[row] = s;

    // bf16 permuted
    if (lane < 16) {
        const int c = lane >> 2;
        const int qq = lane & 3;
        const float* rr = src + (size_t)row * DD + c * 32;
        uint4 u;
        u.x = pack_bf16(rr[2 * qq],      rr[2 * qq + 1]);
        u.y = pack_bf16(rr[2 * qq + 8],  rr[2 * qq + 9]);
        u.z = pack_bf16(rr[16 + 2 * qq],     rr[16 + 2 * qq + 1]);
        u.w = pack_bf16(rr[16 + 2 * qq + 8], rr[16 + 2 * qq + 9]);
        db[(size_t)c * (NR * 4) + (size_t)row * 4 + qq] = u;
    }
}

// ---- main kernel: 128x128 CTA tile, 8 warps (4m x 2n), warp tile 32x64 -----
__global__ __launch_bounds__(256, 2)
void rbf_mma_kernel(const float* __restrict__ sigma,
                    float* __restrict__ out,
                    int Mtot) {
    extern __shared__ char smem[];
    const int tid = threadIdx.x;
    const int lane = tid & 31;
    const int wid = tid >> 5;
    const int q = lane & 3;
    const int g = lane >> 2;
    const int wm = wid & 3;
    const int wn = wid >> 2;

    const int row0 = blockIdx.y * 128;
    const int col0 = blockIdx.x * 128;
    const int rowW = row0 + wm * 32;
    const int colW = col0 + wn * 64;

    float acc[2][8][4];
    #pragma unroll
    for (int mt = 0; mt < 2; mt++)
        #pragma unroll
        for (int j = 0; j < 8; j++)
            #pragma unroll
            for (int e = 0; e < 4; e++) acc[mt][j][e] = 0.0f;

    // ======================= PHASE 1: bf16 estimate ========================
    const int t7 = tid & 127;
    const bool isA = tid < 128;
    const uint4* gf = (isA ? g_Xb + (size_t)row0 * 4 : g_Yb + (size_t)col0 * 4) + t7;
    const int foff = (isA ? 0 : 8192) + t7 * 16;

    {   // prologue: chunk 0 -> buf 0 (pure linear copy)
        uint4 st[4];
        #pragma unroll
        for (int i = 0; i < 4; i++) st[i] = gf[i * 128];
        #pragma unroll
        for (int i = 0; i < 4; i++) *(uint4*)(smem + foff + i * 2048) = st[i];
    }
    __syncthreads();

    const int aOff = (wm * 32 + g) * 64 + q * 16;
    const int bOff = 8192 + (wn * 64 + g) * 64 + q * 16;

    #pragma unroll 2
    for (int c = 0; c < NCHUNK; c++) {
        char* bs = smem + (c & 1) * P1_STAGE;
        char* bd = smem + ((c + 1) & 1) * P1_STAGE + foff;
        const uint4* gn = gf + (size_t)(c + 1) * (NR * 4);
        const bool pf = (c < NCHUNK - 1);

        uint4 st[4];
        if (pf) {
            #pragma unroll
            for (int i = 0; i < 4; i++) st[i] = gn[i * 128];
        }

        // A fragments: rows g+{0,8,16,24}; one LDS.128 each covers both k16 halves
        uint4 A0 = *(const uint4*)(bs + aOff);
        uint4 A1 = *(const uint4*)(bs + aOff + 512);
        uint4 A2 = *(const uint4*)(bs + aOff + 1024);
        uint4 A3 = *(const uint4*)(bs + aOff + 1536);

        #define JB(j_)                                                           \
        do {                                                                     \
            uint4 B = *(const uint4*)(bs + bOff + (j_) * 512);                   \
            mma16(acc[0][j_], A0.x, A1.x, A0.y, A1.y, B.x, B.y);                 \
            mma16(acc[0][j_], A0.z, A1.z, A0.w, A1.w, B.z, B.w);                 \
            mma16(acc[1][j_], A2.x, A3.x, A2.y, A3.y, B.x, B.y);                 \
            mma16(acc[1][j_], A2.z, A3.z, A2.w, A3.w, B.z, B.w);                 \
        } while (0)

        JB(0); JB(1); JB(2); JB(3);
        if (pf) {
            *(uint4*)(bd)        = st[0];
            *(uint4*)(bd + 2048) = st[1];
        }
        JB(4); JB(5); JB(6); JB(7);
        if (pf) {
            *(uint4*)(bd + 4096) = st[2];
            *(uint4*)(bd + 6144) = st[3];
        }
        __syncthreads();
        #undef JB
    }

    // ======================= DECISION ======================================
    float sv = sigma[0];
    float inv = 1.0f / (sv * sv + 1e-9f);

    // bf16 dot error <= 2^-9*(x2+y2) => 2*err <= 0.004*(x2+y2); margin 0.008.
    // u = inv*(2*dot - (x2+y2) + 0.008*(x2+y2)) = inv*(2*dot - 0.992*(x2+y2)).
    // If u < -105 for the whole tile, exp underflows to exactly 0.0f for both
    // this kernel and the fp32 reference.
    int need = 0;
    #pragma unroll
    for (int mt = 0; mt < 2; mt++) {
        const int r0 = rowW + mt * 16 + g;
        const float x2a = g_x2[r0];
        const float x2b = g_x2[r0 + 8];
        #pragma unroll
        for (int j = 0; j < 8; j++) {
            const int cb = colW + j * 8 + 2 * q;
            const float y0 = g_y2[cb];
            const float y1 = g_y2[cb + 1];
            const float* c = acc[mt][j];
            float u0 = inv * (2.0f * c[0] - 0.992f * (x2a + y0));
            float u1 = inv * (2.0f * c[1] - 0.992f * (x2a + y1));
            float u2 = inv * (2.0f * c[2] - 0.992f * (x2b + y0));
            float u3 = inv * (2.0f * c[3] - 0.992f * (x2b + y1));
            float mx = fmaxf(fmaxf(u0, u1), fmaxf(u2, u3));
            need |= (mx >= -105.0f);
        }
    }
    int doit = __syncthreads_or(need);

    if (!doit) {
        // whole tile underflows: fully coalesced streaming zero write
        float4 z = make_float4(0.0f, 0.0f, 0.0f, 0.0f);
        float* dst = out + (size_t)(row0 + wid * 16) * Mtot + col0 + lane * 4;
        #pragma unroll
        for (int r = 0; r < 16; r++)
            __stcs((float4*)(dst + (size_t)r * Mtot), z);
        return;
    }

    // ======================= PHASE 2: full 3-pass tf32 =====================
    #pragma unroll
    for (int mt = 0; mt < 2; mt++)
        #pragma unroll
        for (int j = 0; j < 8; j++)
            #pragma unroll
            for (int e = 0; e < 4; e++) acc[mt][j][e] = 0.0f;

    const int region = tid >> 6;
    const int t6 = tid & 63;
    const float* gsrc2;
    int gr2;
    if      (region == 0) { gsrc2 = g_Xhi; gr2 = row0; }
    else if (region == 1) { gsrc2 = g_Xlo; gr2 = row0; }
    else if (region == 2) { gsrc2 = g_Yhi; gr2 = col0; }
    else                  { gsrc2 = g_Ylo; gr2 = col0; }
    const float* g2 = gsrc2 + (size_t)gr2 * 16 + (size_t)t6 * 4;
    const int soff2 = region * 8192 + t6 * 16;

    {   // prologue: stage 0 -> buf 0
        float4 st[8];
        #pragma unroll
        for (int c = 0; c < 8; c++)
            st[c] = *(const float4*)(g2 + (size_t)c * 256);
        #pragma unroll
        for (int c = 0; c < 8; c++)
            *(float4*)(smem + soff2 + c * 1024) = st[c];
    }
    __syncthreads();

    const int aOff2 = (wm * 32 + g) * 64 + q * 16;
    const int bOff2 = 16384 + (wn * 64 + g) * 64 + q * 16;

    #pragma unroll 2
    for (int s = 0; s < NSTAGE2; s++) {
        char* bs = smem + (s & 1) * P2_STAGE;
        char* bd = smem + ((s + 1) & 1) * P2_STAGE + soff2;
        const float* gn = g2 + (size_t)(s + 1) * (NR * 16);
        const bool pf = (s < NSTAGE2 - 1);

        float4 st[4];
        if (pf) {
            #pragma unroll
            for (int c = 0; c < 4; c++)
                st[c] = *(const float4*)(gn + (size_t)c * 256);
        }

        float4 ah[4], al[4];
        #pragma unroll
        for (int r = 0; r < 4; r++) {
            ah[r] = *(const float4*)(bs + aOff2 + r * 512);
            al[r] = *(const float4*)(bs + aOff2 + 8192 + r * 512);
        }

        #define J2(j_)                                                           \
        do {                                                                     \
            float4 bh = *(const float4*)(bs + bOff2 + (j_) * 512);               \
            float4 bl = *(const float4*)(bs + bOff2 + 8192 + (j_) * 512);        \
            float* c0 = acc[0][j_];                                              \
            mma8(c0, ah[0].x, ah[1].x, ah[0].y, ah[1].y, bh.x, bh.y);            \
            mma8(c0, ah[0].x, ah[1].x, ah[0].y, ah[1].y, bl.x, bl.y);            \
            mma8(c0, al[0].x, al[1].x, al[0].y, al[1].y, bh.x, bh.y);            \
            mma8(c0, ah[0].z, ah[1].z, ah[0].w, ah[1].w, bh.z, bh.w);            \
            mma8(c0, ah[0].z, ah[1].z, ah[0].w, ah[1].w, bl.z, bl.w);            \
            mma8(c0, al[0].z, al[1].z, al[0].w, al[1].w, bh.z, bh.w);            \
            float* c1 = acc[1][j_];                                              \
            mma8(c1, ah[2].x, ah[3].x, ah[2].y, ah[3].y, bh.x, bh.y);            \
            mma8(c1, ah[2].x, ah[3].x, ah[2].y, ah[3].y, bl.x, bl.y);            \
            mma8(c1, al[2].x, al[3].x, al[2].y, al[3].y, bh.x, bh.y);            \
            mma8(c1, ah[2].z, ah[3].z, ah[2].w, ah[3].w, bh.z, bh.w);            \
            mma8(c1, ah[2].z, ah[3].z, ah[2].w, ah[3].w, bl.z, bl.w);            \
            mma8(c1, al[2].z, al[3].z, al[2].w, al[3].w, bh.z, bh.w);            \
        } while (0)

        J2(0); J2(1); J2(2); J2(3);
        if (pf) {
            #pragma unroll
            for (int c = 0; c < 4; c++)
                *(float4*)(bd + c * 1024) = st[c];
            #pragma unroll
            for (int c = 0; c < 4; c++)
                st[c] = *(const float4*)(gn + (size_t)(c + 4) * 256);
        }
        J2(4); J2(5); J2(6); J2(7);
        if (pf) {
            #pragma unroll
            for (int c = 0; c < 4; c++)
                *(float4*)(bd + (c + 4) * 1024) = st[c];
        }
        __syncthreads();
        #undef J2
    }

    // ======================= EPILOGUE ======================================
    #pragma unroll
    for (int mt = 0; mt < 2; mt++) {
        const int r0 = rowW + mt * 16 + g;
        const float x2a = g_x2[r0];
        const float x2b = g_x2[r0 + 8];
        #pragma unroll
        for (int j = 0; j < 8; j++) {
            const int cb = colW + j * 8 + 2 * q;
            const float y0 = g_y2[cb];
            const float y1 = g_y2[cb + 1];
            const float* c = acc[mt][j];
            float a0 = inv * (2.0f * c[0] - x2a - y0);
            float a1 = inv * (2.0f * c[1] - x2a - y1);
            float a2 = inv * (2.0f * c[2] - x2b - y0);
            float a3 = inv * (2.0f * c[3] - x2b - y1);
            float mx = fmaxf(fmaxf(a0, a1), fmaxf(a2, a3));
            float2 o0, o1;
            if (__any_sync(0xffffffffu, mx > -104.0f)) {
                o0.x = __expf(a0);
                o0.y = __expf(a1);
                o1.x = __expf(a2);
                o1.y = __expf(a3);
            } else {
                o0.x = 0.0f; o0.y = 0.0f; o1.x = 0.0f; o1.y = 0.0f;
            }
            *(float2*)(out + (size_t)r0 * Mtot + cb)       = o0;
            *(float2*)(out + (size_t)(r0 + 8) * Mtot + cb) = o1;
        }
    }
}

// ----------------------------------------------------------------------------
extern "C" void kernel_launch(void* const* d_in, const int* in_sizes, int n_in,
                              void* d_out, int out_size) {
    const float* X = (const float*)d_in[0];
    const float* Y = (const float*)d_in[1];
    const float* sigma = (const float*)d_in[2];
    float* out = (float*)d_out;

    const int D = 128;
    const int n = in_sizes[0] / D;   // 8192
    const int m = in_sizes[1] / D;   // 8192

    cudaFuncSetAttribute(rbf_mma_kernel,
                         cudaFuncAttributeMaxDynamicSharedMemorySize, SMEM_TOTAL);

    {   // bf16 + tf32 hi/lo splits + norms
        int warps = n + m;
        int threads = 256;
        int blocks = (warps * 32 + threads - 1) / threads;
        prep_kernel<<<blocks, threads>>>(X, Y, n, m);
    }

    {   // adaptive HMMA GEMM + exp
        dim3 grid(m / 128, n / 128);
        rbf_mma_kernel<<<grid, 256, SMEM_TOTAL>>>(sigma, out, m);
    }
}